// round 11
// baseline (speedup 1.0000x reference)
#include <cuda_runtime.h>
#include <cuda_fp16.h>
#include <stdint.h>

#define NN 4096
#define H 64
#define FIN 8
#define MTILE 32
#define BK 64
#define NC (NN / BK)          /* 64 k-chunks */
#define HSCL  (1.0f / 1024.0f)
#define HUNSCL 1024.0f

// -------- persistent scratch (no device allocations allowed) --------
__device__ __half g_Af[(size_t)NN * NN];     // A in fp16, row-major
__device__ __half g_hTf[(size_t)H * NN];     // (h*HSCL)^T fp16: [n][k]
__device__ float g_h0[NN * H];
__device__ float g_h1[NN * H];
__device__ float g_si[NN];
__device__ float g_sj[NN];

// ---------------- helpers ----------------
__device__ __forceinline__ uint32_t smem_u32(const void* p) {
    uint32_t a;
    asm("{ .reg .u64 t; cvta.to.shared.u64 t, %1; cvt.u32.u64 %0, t; }"
        : "=r"(a) : "l"(p));
    return a;
}
#define SW128(off) ((off) ^ (((off) >> 3) & 0x70))
#define CP_ASYNC16(dst, src) \
    asm volatile("cp.async.cg.shared.global [%0], [%1], 16;" :: "r"(dst), "l"(src))
#define CP_COMMIT() asm volatile("cp.async.commit_group;" ::: "memory")
#define CP_WAIT(n)  asm volatile("cp.async.wait_group %0;" :: "n"(n) : "memory")

#define LDSM_X4(r0, r1, r2, r3, addr) \
    asm volatile("ldmatrix.sync.aligned.m8n8.x4.shared.b16 {%0,%1,%2,%3}, [%4];" \
        : "=r"(r0), "=r"(r1), "=r"(r2), "=r"(r3) : "r"(addr))

#define MMA_F16(c, a, b0v, b1v) \
    asm volatile("mma.sync.aligned.m16n8k16.row.col.f32.f16.f16.f32 " \
        "{%0,%1,%2,%3}, {%4,%5,%6,%7}, {%8,%9}, {%0,%1,%2,%3};" \
        : "+f"((c)[0]), "+f"((c)[1]), "+f"((c)[2]), "+f"((c)[3]) \
        : "r"((a)[0]), "r"((a)[1]), "r"((a)[2]), "r"((a)[3]), "r"(b0v), "r"(b1v))

// ============================================================
// convA: A fp32 -> fp16 (once per launch; A in [0,1))
// ============================================================
__global__ void convA_kernel(const float* __restrict__ A) {
    size_t t = (size_t)blockIdx.x * 256 + threadIdx.x;   // one per 8 floats
    const float4* a4 = reinterpret_cast<const float4*>(A);
    float4 a = a4[2 * t], b = a4[2 * t + 1];
    __half2 p0 = __floats2half2_rn(a.x, a.y);
    __half2 p1 = __floats2half2_rn(a.z, a.w);
    __half2 p2 = __floats2half2_rn(b.x, b.y);
    __half2 p3 = __floats2half2_rn(b.z, b.w);
    uint4 u;
    u.x = *reinterpret_cast<uint32_t*>(&p0);
    u.y = *reinterpret_cast<uint32_t*>(&p1);
    u.z = *reinterpret_cast<uint32_t*>(&p2);
    u.w = *reinterpret_cast<uint32_t*>(&p3);
    reinterpret_cast<uint4*>(g_Af)[t] = u;
}

// ============================================================
// Encoder: h0 = relu(X @ W_enc^T + b_enc); writes h fp32 + scaled hT fp16
// ============================================================
__global__ void enc_kernel(const float* __restrict__ X,
                           const float* __restrict__ We,
                           const float* __restrict__ be,
                           float* __restrict__ hout) {
    __shared__ float Ws[H][FIN];
    __shared__ float bs[H];
    __shared__ float hsm[4][64];
    int tid = threadIdx.x;
    for (int i = tid; i < H * FIN; i += 256) Ws[i / FIN][i % FIN] = We[i];
    if (tid < H) bs[tid] = be[tid];
    __syncthreads();
    int idx = blockIdx.x * 256 + tid;
    int i = idx >> 6, j = idx & 63;
    const float* xr = X + i * FIN;
    float acc = bs[j];
#pragma unroll
    for (int f = 0; f < FIN; f++) acc += xr[f] * Ws[j][f];
    float v = fmaxf(acc, 0.0f);
    hout[idx] = v;
    hsm[tid >> 6][j] = v;
    __syncthreads();
    int n = tid >> 2, kl = tid & 3;
    int kb = blockIdx.x * 4;
    g_hTf[(size_t)n * NN + kb + kl] = __float2half_rn(hsm[kl][n] * HSCL);
}

// ============================================================
// Fused GNN layer: one CTA = 32 rows. Full-K HMMA GEMM (hn = A@h),
// then inline MLP: hout = relu([h, hn] @ W^T + b), writes h fp32 +
// scaled hT fp16; last layer computes s_i/s_j instead of hT.
// grid 128 x 256 thr. 3-stage cp.async pipeline.
// ============================================================
#define ASZ 4096                 /* 32 x 128B */
#define BSZ 8192                 /* 64 x 128B */
#define STG (ASZ + BSZ)          /* 12288 */
#define W1_OFF (3 * STG)         /* 36864 */
#define W2_OFF (W1_OFF + 17408)  /* 54272 */
#define HS_OFF (W2_OFF + 17408)  /* 71680 */
#define HN_OFF (HS_OFF + 8320)   /* 80000 */
#define HO_OFF 0                 /* aliases pipeline stages (post-mainloop) */
#define SMEM_TOTAL (HN_OFF + 8320)   /* 88320 */
#define WSTR 68

__device__ __forceinline__ void load_chunk32(uint32_t smem_base, int s, int k0,
                                             int tid, int mbase) {
    const char* Ab = reinterpret_cast<const char*>(g_Af);
    const char* Hb = reinterpret_cast<const char*>(g_hTf);
    uint32_t abase = smem_base + s * STG;
    uint32_t bbase = abase + ASZ;
    {   // A: 32 rows x 128B = 256 x 16B, exactly 1 per thread
        int row = tid >> 3, j = tid & 7;
        uint32_t off = (uint32_t)(row * 128 + j * 16);
        const char* src = Ab + ((size_t)(mbase + row) * NN + k0) * 2 + j * 16;
        CP_ASYNC16(abase + SW128(off), src);
    }
#pragma unroll
    for (int it = 0; it < 2; it++) {   // B: 64 n-rows x 128B
        int c = tid + it * 256;
        int n = c >> 3, j = c & 7;
        uint32_t off = (uint32_t)(n * 128 + j * 16);
        const char* src = Hb + ((size_t)n * NN + k0) * 2 + j * 16;
        CP_ASYNC16(bbase + SW128(off), src);
    }
    CP_COMMIT();
}

__global__ __launch_bounds__(256, 1)
void layer_kernel(const float* __restrict__ hin, const float* __restrict__ W,
                  const float* __restrict__ b, float* __restrict__ hout,
                  int last, const float* __restrict__ Wedge,
                  const float* __restrict__ bedge) {
    extern __shared__ __align__(1024) char smem[];
    const uint32_t smem_base = smem_u32(smem);
    float* W1T = reinterpret_cast<float*>(smem + W1_OFF);  // [c][col], WSTR
    float* W2T = reinterpret_cast<float*>(smem + W2_OFF);
    float* h_s = reinterpret_cast<float*>(smem + HS_OFF);  // [32][65]
    float* hn_s = reinterpret_cast<float*>(smem + HN_OFF); // [32][65]
    float* ho_s = reinterpret_cast<float*>(smem + HO_OFF); // [32][65]

    const int tid = threadIdx.x;
    const int wid = tid >> 5;
    const int lane = tid & 31;
    const int warp_m = wid >> 2;        // 0..1 -> 16 rows each
    const int warp_n = wid & 3;         // 0..3 -> 16 cols each
    const int mbase = blockIdx.x * MTILE;

    float acc[2][4];
#pragma unroll
    for (int nt = 0; nt < 2; nt++)
#pragma unroll
        for (int e = 0; e < 4; e++) acc[nt][e] = 0.0f;

    const int a_row = lane & 15;
    const int a_khalf = (lane >> 4) * 16;
    const int b_m = lane >> 3;
    const int b_r = lane & 7;
    const int b_n = ((b_m >> 1) << 3) + b_r;
    const int b_khalf = (b_m & 1) * 16;

    // prologue: 2 chunks in flight, then stage W + h while they land
    load_chunk32(smem_base, 0, 0, tid, mbase);
    load_chunk32(smem_base, 1, BK, tid, mbase);
    for (int i = tid; i < H * H; i += 256) {
        int col = i >> 6, c = i & 63;
        W1T[c * WSTR + col] = W[col * 128 + c];
        W2T[c * WSTR + col] = W[col * 128 + H + c];
    }
    for (int i = tid; i < MTILE * H; i += 256) {
        int r = i >> 6, c = i & 63;
        h_s[r * 65 + c] = hin[(size_t)(mbase + r) * H + c];
    }

#pragma unroll 1
    for (int i = 0; i < NC; i++) {
        if (i + 2 < NC) {
            load_chunk32(smem_base, (i + 2) % 3, (i + 2) * BK, tid, mbase);
            CP_WAIT(2);
        } else if (i + 1 < NC) {
            CP_WAIT(1);
        } else {
            CP_WAIT(0);
        }
        __syncthreads();

        const uint32_t abase = smem_base + (i % 3) * STG;
        const uint32_t bbase = abase + ASZ;
#pragma unroll
        for (int ks = 0; ks < 4; ks++) {
            uint32_t bb[4];
            uint32_t boff = (uint32_t)((warp_n * 16 + b_n) * 128 +
                                       ks * 32 + b_khalf);
            LDSM_X4(bb[0], bb[1], bb[2], bb[3], bbase + SW128(boff));
            uint32_t aa[4];
            uint32_t aoff = (uint32_t)((warp_m * 16 + a_row) * 128 +
                                       ks * 32 + a_khalf);
            LDSM_X4(aa[0], aa[1], aa[2], aa[3], abase + SW128(aoff));
            MMA_F16(acc[0], aa, bb[0], bb[1]);
            MMA_F16(acc[1], aa, bb[2], bb[3]);
        }
        __syncthreads();
    }

    // hn (unscaled) -> smem
    {
        const int r = warp_m * 16 + (lane >> 2);
        const int c0 = warp_n * 16 + (lane & 3) * 2;
#pragma unroll
        for (int nt = 0; nt < 2; nt++) {
            int col = c0 + nt * 8;
            hn_s[r * 65 + col]           = acc[nt][0] * HUNSCL;
            hn_s[r * 65 + col + 1]       = acc[nt][1] * HUNSCL;
            hn_s[(r + 8) * 65 + col]     = acc[nt][2] * HUNSCL;
            hn_s[(r + 8) * 65 + col + 1] = acc[nt][3] * HUNSCL;
        }
    }
    __syncthreads();

    // MLP: thread tile 4 cols x 2 rows
    const int tx = tid & 15;
    const int ty = tid >> 4;
    const int col0 = tx * 4;
    const int r0 = ty * 2;
    float o[2][4];
#pragma unroll
    for (int r = 0; r < 2; r++)
#pragma unroll
        for (int j = 0; j < 4; j++) o[r][j] = 0.0f;
#pragma unroll
    for (int c = 0; c < H; c++) {
        float4 w1 = *reinterpret_cast<const float4*>(&W1T[c * WSTR + col0]);
        float4 w2 = *reinterpret_cast<const float4*>(&W2T[c * WSTR + col0]);
#pragma unroll
        for (int r = 0; r < 2; r++) {
            float hv = h_s[(r0 + r) * 65 + c];
            float hnv = hn_s[(r0 + r) * 65 + c];
            o[r][0] += hv * w1.x + hnv * w2.x;
            o[r][1] += hv * w1.y + hnv * w2.y;
            o[r][2] += hv * w1.z + hnv * w2.z;
            o[r][3] += hv * w1.w + hnv * w2.w;
        }
    }
#pragma unroll
    for (int r = 0; r < 2; r++) {
#pragma unroll
        for (int j = 0; j < 4; j++) {
            float v = fmaxf(o[r][j] + b[col0 + j], 0.0f);
            hout[(size_t)(mbase + r0 + r) * H + col0 + j] = v;
            ho_s[(r0 + r) * 65 + col0 + j] = v;
        }
    }
    __syncthreads();

    if (!last) {
        // transpose-write scaled hT fp16: n = i>>5, kl = i&31
        for (int i = tid; i < H * MTILE; i += 256) {
            int n = i >> 5, kl = i & 31;
            g_hTf[(size_t)n * NN + mbase + kl] =
                __float2half_rn(ho_s[kl * 65 + n] * HSCL);
        }
    } else {
        if (tid < MTILE) {
            int r = tid;
            float a = 0.0f, bb2 = 0.0f;
#pragma unroll
            for (int c = 0; c < H; c++) {
                float hv = ho_s[r * 65 + c];
                a += hv * Wedge[c];
                bb2 += hv * Wedge[H + c];
            }
            g_si[mbase + r] = a + bedge[0];
            g_sj[mbase + r] = bb2;
        }
    }
}

// ============================================================
// scores[i][j] = s_i[i] + s_j[j], diag zeroed. float4 stores.
// ============================================================
__global__ void scores_kernel(float* __restrict__ out) {
    int idx = blockIdx.x * 256 + threadIdx.x;
    int i = idx >> 10;
    int j4 = (idx & 1023) << 2;
    float si = g_si[i];
    float4 sj = *reinterpret_cast<const float4*>(&g_sj[j4]);
    float4 v = make_float4(si + sj.x, si + sj.y, si + sj.z, si + sj.w);
    int d = i - j4;
    if (d >= 0 && d < 4) ((float*)&v)[d] = 0.0f;
    reinterpret_cast<float4*>(out)[idx] = v;
}

// ============================================================
extern "C" void kernel_launch(void* const* d_in, const int* in_sizes, int n_in,
                              void* d_out, int out_size) {
    const float* X     = (const float*)d_in[0];
    const float* Adj   = (const float*)d_in[1];
    const float* We    = (const float*)d_in[2];
    const float* be    = (const float*)d_in[3];
    const float* Wl[3] = {(const float*)d_in[4], (const float*)d_in[6],
                          (const float*)d_in[8]};
    const float* bl[3] = {(const float*)d_in[5], (const float*)d_in[7],
                          (const float*)d_in[9]};
    const float* Wedge = (const float*)d_in[10];
    const float* bedge = (const float*)d_in[11];
    float* out = (float*)d_out;

    cudaFuncSetAttribute(layer_kernel,
                         cudaFuncAttributeMaxDynamicSharedMemorySize, SMEM_TOTAL);

    float *ph0 = nullptr, *ph1 = nullptr;
    cudaGetSymbolAddress((void**)&ph0, g_h0);
    cudaGetSymbolAddress((void**)&ph1, g_h1);

    convA_kernel<<<(NN * NN / 8) / 256, 256>>>(Adj);
    enc_kernel<<<NN * H / 256, 256>>>(X, We, be, ph0);

    float* hcur = ph0;
    float* hnext = ph1;
    for (int l = 0; l < 3; l++) {
        layer_kernel<<<NN / MTILE, 256, SMEM_TOTAL>>>(
            hcur, Wl[l], bl[l], hnext, (l == 2) ? 1 : 0, Wedge, bedge);
        float* t = hcur; hcur = hnext; hnext = t;
    }

    scores_kernel<<<(NN / 4) * NN / 256, 256>>>(out);
}

// round 13
// speedup vs baseline: 1.0545x; 1.0545x over previous
#include <cuda_runtime.h>
#include <cuda_fp16.h>
#include <stdint.h>

#define NN 4096
#define H 64
#define FIN 8
#define SPLITK 8
#define KCHUNK (NN / SPLITK)   /* 512 */
#define NCHUNK (KCHUNK / 64)   /* 8 chunks of K=64 */
#define MROWS 8                /* small rows/block -> 512 blocks -> occupancy */
#define HSCL  (1.0f / 1024.0f)   /* exact pow2: keeps h^T inside fp16 range */
#define HUNSCL 1024.0f

// -------- persistent scratch (no device allocations allowed) --------
__device__ __half g_Af[(size_t)NN * NN];     // A in fp16, row-major
__device__ __half g_hTf[(size_t)H * NN];     // (h*HSCL)^T fp16: [n][k], K-major
__device__ float g_h0[NN * H];
__device__ float g_h1[NN * H];
__device__ float g_part[SPLITK][NN * H];
__device__ float g_si[NN];
__device__ float g_sj[NN];

// ---------------- helpers ----------------
__device__ __forceinline__ uint32_t smem_u32(const void* p) {
    uint32_t a;
    asm("{ .reg .u64 t; cvta.to.shared.u64 t, %1; cvt.u32.u64 %0, t; }"
        : "=r"(a) : "l"(p));
    return a;
}
#define SW128(off) ((off) ^ (((off) >> 3) & 0x70))
#define CP_ASYNC16(dst, src) \
    asm volatile("cp.async.cg.shared.global [%0], [%1], 16;" :: "r"(dst), "l"(src))
#define CP_COMMIT() asm volatile("cp.async.commit_group;" ::: "memory")
#define CP_WAIT(n)  asm volatile("cp.async.wait_group %0;" :: "n"(n) : "memory")

#define LDSM_X4(r0, r1, r2, r3, addr) \
    asm volatile("ldmatrix.sync.aligned.m8n8.x4.shared.b16 {%0,%1,%2,%3}, [%4];" \
        : "=r"(r0), "=r"(r1), "=r"(r2), "=r"(r3) : "r"(addr))

#define MMA_F16(c, a, b0v, b1v) \
    asm volatile("mma.sync.aligned.m16n8k16.row.col.f32.f16.f16.f32 " \
        "{%0,%1,%2,%3}, {%4,%5,%6,%7}, {%8,%9}, {%0,%1,%2,%3};" \
        : "+f"((c)[0]), "+f"((c)[1]), "+f"((c)[2]), "+f"((c)[3]) \
        : "r"((a)[0]), "r"((a)[1]), "r"((a)[2]), "r"((a)[3]), "r"(b0v), "r"(b1v))

// ============================================================
// convA: A fp32 -> fp16 (once per launch; A in [0,1) — safe range)
// ============================================================
__global__ void convA_kernel(const float* __restrict__ A) {
    size_t t = (size_t)blockIdx.x * 256 + threadIdx.x;   // one per 8 floats
    const float4* a4 = reinterpret_cast<const float4*>(A);
    float4 a = a4[2 * t], b = a4[2 * t + 1];
    __half2 p0 = __floats2half2_rn(a.x, a.y);
    __half2 p1 = __floats2half2_rn(a.z, a.w);
    __half2 p2 = __floats2half2_rn(b.x, b.y);
    __half2 p3 = __floats2half2_rn(b.z, b.w);
    uint4 u;
    u.x = *reinterpret_cast<uint32_t*>(&p0);
    u.y = *reinterpret_cast<uint32_t*>(&p1);
    u.z = *reinterpret_cast<uint32_t*>(&p2);
    u.w = *reinterpret_cast<uint32_t*>(&p3);
    reinterpret_cast<uint4*>(g_Af)[t] = u;
}

// ============================================================
// Encoder: h0 = relu(X @ W_enc^T + b_enc); also writes scaled hT fp16.
// Each block: 4 rows x 64 cols.
// ============================================================
__global__ void enc_kernel(const float* __restrict__ X,
                           const float* __restrict__ We,
                           const float* __restrict__ be,
                           float* __restrict__ hout) {
    __shared__ float Ws[H][FIN];
    __shared__ float bs[H];
    __shared__ float hsm[4][64];
    int tid = threadIdx.x;
    for (int i = tid; i < H * FIN; i += 256) Ws[i / FIN][i % FIN] = We[i];
    if (tid < H) bs[tid] = be[tid];
    __syncthreads();
    int idx = blockIdx.x * 256 + tid;
    int i = idx >> 6, j = idx & 63;
    const float* xr = X + i * FIN;
    float acc = bs[j];
#pragma unroll
    for (int f = 0; f < FIN; f++) acc += xr[f] * Ws[j][f];
    float v = fmaxf(acc, 0.0f);
    hout[idx] = v;
    hsm[tid >> 6][j] = v;
    __syncthreads();
    // transpose-write scaled hT fp16: n = tid>>2 (0..63), kl = tid&3 (0..3)
    int n = tid >> 2, kl = tid & 3;
    int kb = blockIdx.x * 4;
    g_hTf[(size_t)n * NN + kb + kl] = __float2half_rn(hsm[kl][n] * HSCL);
}

// ============================================================
// fp16 HMMA GEMM: part[sk] = A[:, sk*512:+512] @ (h*HSCL)[sk*512:+512]
// grid (32, 8) x 256 thr. CTA tile 128x64, BK=64, 2-stage cp.async.
// Warp grid 2x4; warp tile 64x16 (4 x m16, 2 x n8). fp32 accum.
// ============================================================
#define STAGE_BYTES 24576       /* 16KB A + 8KB B */
#define B_SOFF 16384
#define SMEM_TOTAL (2 * STAGE_BYTES)   /* 49152 */

__device__ __forceinline__ void load_chunk(uint32_t smem_base, int s, int k0,
                                           int tid, int mbase) {
    const char* Ab = reinterpret_cast<const char*>(g_Af);
    const char* Hb = reinterpret_cast<const char*>(g_hTf);
    uint32_t abase = smem_base + s * STAGE_BYTES;
    uint32_t bbase = smem_base + B_SOFF + s * STAGE_BYTES;
#pragma unroll
    for (int it = 0; it < 4; it++) {                 // A: 128 rows x 128B
        int c = tid + it * 256;
        int row = c >> 3, j = c & 7;
        uint32_t off = (uint32_t)(row * 128 + j * 16);
        const char* src = Ab + ((size_t)(mbase + row) * NN + k0) * 2 + j * 16;
        CP_ASYNC16(abase + SW128(off), src);
    }
#pragma unroll
    for (int it = 0; it < 2; it++) {                 // B: 64 n-rows x 128B
        int c = tid + it * 256;
        int n = c >> 3, j = c & 7;
        uint32_t off = (uint32_t)(n * 128 + j * 16);
        const char* src = Hb + ((size_t)n * NN + k0) * 2 + j * 16;
        CP_ASYNC16(bbase + SW128(off), src);
    }
    CP_COMMIT();
}

__global__ __launch_bounds__(256, 2)
void gemm_mma_kernel() {
    extern __shared__ __align__(1024) char smem[];
    const uint32_t smem_base = smem_u32(smem);
    const int tid = threadIdx.x;
    const int wid = tid >> 5;
    const int lane = tid & 31;
    const int warp_m = wid >> 2;        // 0..1 -> 64 rows each
    const int warp_n = wid & 3;         // 0..3 -> 16 cols each
    const int mbase = blockIdx.x * 128;
    const int kbase = blockIdx.y * KCHUNK;

    float acc[4][2][4];
#pragma unroll
    for (int mt = 0; mt < 4; mt++)
#pragma unroll
        for (int nt = 0; nt < 2; nt++)
#pragma unroll
            for (int e = 0; e < 4; e++) acc[mt][nt][e] = 0.0f;

    // ldmatrix lane addressing (constant per thread)
    const int a_row = lane & 15;
    const int a_khalf = (lane >> 4) * 16;
    const int b_m = lane >> 3;
    const int b_r = lane & 7;
    const int b_n = ((b_m >> 1) << 3) + b_r;
    const int b_khalf = (b_m & 1) * 16;

    load_chunk(smem_base, 0, kbase, tid, mbase);

#pragma unroll 1
    for (int i = 0; i < NCHUNK; i++) {
        const int s = i & 1;
        if (i + 1 < NCHUNK) {
            load_chunk(smem_base, (i + 1) & 1, kbase + (i + 1) * 64, tid, mbase);
            CP_WAIT(1);
        } else {
            CP_WAIT(0);
        }
        __syncthreads();

        const uint32_t abase = smem_base + s * STAGE_BYTES;
        const uint32_t bbase = smem_base + B_SOFF + s * STAGE_BYTES;
#pragma unroll
        for (int ks = 0; ks < 4; ks++) {
            uint32_t b[4];
            {
                uint32_t off = (uint32_t)((warp_n * 16 + b_n) * 128 +
                                          ks * 32 + b_khalf);
                LDSM_X4(b[0], b[1], b[2], b[3], bbase + SW128(off));
            }
#pragma unroll
            for (int mt = 0; mt < 4; mt++) {
                uint32_t a[4];
                uint32_t off = (uint32_t)((warp_m * 64 + mt * 16 + a_row) * 128 +
                                          ks * 32 + a_khalf);
                LDSM_X4(a[0], a[1], a[2], a[3], abase + SW128(off));
                MMA_F16(acc[mt][0], a, b[0], b[1]);
                MMA_F16(acc[mt][1], a, b[2], b[3]);
            }
        }
        __syncthreads();
    }

    // epilogue: write 64x16 warp tile to g_part[blockIdx.y]
    float* out = g_part[blockIdx.y];
    const int r0 = mbase + warp_m * 64 + (lane >> 2);
    const int c0 = warp_n * 16 + (lane & 3) * 2;
#pragma unroll
    for (int mt = 0; mt < 4; mt++) {
#pragma unroll
        for (int nt = 0; nt < 2; nt++) {
            int col = c0 + nt * 8;
            float2 lo = make_float2(acc[mt][nt][0], acc[mt][nt][1]);
            float2 hi = make_float2(acc[mt][nt][2], acc[mt][nt][3]);
            *reinterpret_cast<float2*>(&out[(size_t)(r0 + mt * 16) * H + col]) = lo;
            *reinterpret_cast<float2*>(&out[(size_t)(r0 + mt * 16 + 8) * H + col]) = hi;
        }
    }
}

// ============================================================
// MLP: hout = relu([h, HUNSCL * sum_sk part_sk] @ W^T + b)
// 512 blocks x 256 thr, 8 rows/block; <=64 regs -> 4 CTAs/SM.
// Writes scaled hT fp16 (non-last); last layer computes s_i/s_j.
// ============================================================
__global__ __launch_bounds__(256, 4)
void mlp_kernel(const float* __restrict__ hin, const float* __restrict__ W,
                const float* __restrict__ b, float* __restrict__ hout,
                int last, const float* __restrict__ Wedge,
                const float* __restrict__ bedge) {
    __shared__ float Ws[H][2 * H + 1];
    __shared__ float h_s[MROWS][H];
    __shared__ float hn_s[MROWS][H];
    __shared__ float ho_s[MROWS][H];
    __shared__ float wedge[2 * H];
    const int tid = threadIdx.x;
    const int rbase = blockIdx.x * MROWS;

    for (int i = tid; i < H * 2 * H; i += 256)
        Ws[i / (2 * H)][i % (2 * H)] = W[i];
    if (last && tid < 2 * H) wedge[tid] = Wedge[tid];
    // stage h and reduced neighbor sums (8 rows x 64 cols = 512 elems)
    for (int i = tid; i < MROWS * H; i += 256) {
        int r = i >> 6, c = i & 63;
        h_s[r][c] = hin[(rbase + r) * H + c];
        float s = 0.0f;
#pragma unroll
        for (int p = 0; p < SPLITK; p++) s += g_part[p][(rbase + r) * H + c];
        hn_s[r][c] = s * HUNSCL;   // undo fp16 range scaling
    }
    __syncthreads();

    const int col = tid & 63;
    const int rg = tid >> 6;  // 0..3, 2 rows each
    const float bias = b[col];
#pragma unroll
    for (int rr = 0; rr < MROWS / 4; rr++) {
        int r = rg * (MROWS / 4) + rr;
        float acc = bias;
#pragma unroll
        for (int c = 0; c < H; c++)
            acc += h_s[r][c] * Ws[col][c] + hn_s[r][c] * Ws[col][H + c];
        float v = fmaxf(acc, 0.0f);
        hout[(rbase + r) * H + col] = v;
        ho_s[r][col] = v;
    }
    __syncthreads();

    if (!last) {
        // transpose-write scaled hT fp16: n = i>>3 (0..63), kl = i&7
        for (int i = tid; i < H * MROWS; i += 256) {
            int n = i >> 3, kl = i & 7;
            g_hTf[(size_t)n * NN + rbase + kl] =
                __float2half_rn(ho_s[kl][n] * HSCL);
        }
    } else {
        // fused s_i / s_j for final h
        if (tid < MROWS) {
            int r = tid;
            float a = 0.0f, bb = 0.0f;
#pragma unroll
            for (int c = 0; c < H; c++) {
                float hv = ho_s[r][c];
                a += hv * wedge[c];
                bb += hv * wedge[H + c];
            }
            g_si[rbase + r] = a + bedge[0];
            g_sj[rbase + r] = bb;
        }
    }
}

// ============================================================
// scores[i][j] = s_i[i] + s_j[j], diag zeroed. float4 stores.
// ============================================================
__global__ void scores_kernel(float* __restrict__ out) {
    int idx = blockIdx.x * 256 + threadIdx.x;
    int i = idx >> 10;
    int j4 = (idx & 1023) << 2;
    float si = g_si[i];
    float4 sj = *reinterpret_cast<const float4*>(&g_sj[j4]);
    float4 v = make_float4(si + sj.x, si + sj.y, si + sj.z, si + sj.w);
    int d = i - j4;
    if (d >= 0 && d < 4) ((float*)&v)[d] = 0.0f;
    reinterpret_cast<float4*>(out)[idx] = v;
}

// ============================================================
extern "C" void kernel_launch(void* const* d_in, const int* in_sizes, int n_in,
                              void* d_out, int out_size) {
    const float* X     = (const float*)d_in[0];
    const float* Adj   = (const float*)d_in[1];
    const float* We    = (const float*)d_in[2];
    const float* be    = (const float*)d_in[3];
    const float* Wl[3] = {(const float*)d_in[4], (const float*)d_in[6],
                          (const float*)d_in[8]};
    const float* bl[3] = {(const float*)d_in[5], (const float*)d_in[7],
                          (const float*)d_in[9]};
    const float* Wedge = (const float*)d_in[10];
    const float* bedge = (const float*)d_in[11];
    float* out = (float*)d_out;

    cudaFuncSetAttribute(gemm_mma_kernel,
                         cudaFuncAttributeMaxDynamicSharedMemorySize, SMEM_TOTAL);

    float *ph0 = nullptr, *ph1 = nullptr;
    cudaGetSymbolAddress((void**)&ph0, g_h0);
    cudaGetSymbolAddress((void**)&ph1, g_h1);

    convA_kernel<<<(NN * NN / 8) / 256, 256>>>(Adj);
    enc_kernel<<<NN * H / 256, 256>>>(X, We, be, ph0);

    float* hcur = ph0;
    float* hnext = ph1;
    for (int l = 0; l < 3; l++) {
        gemm_mma_kernel<<<dim3(NN / 128, SPLITK), 256, SMEM_TOTAL>>>();
        mlp_kernel<<<NN / MROWS, 256>>>(hcur, Wl[l], bl[l], hnext,
                                        (l == 2) ? 1 : 0, Wedge, bedge);
        float* t = hcur; hcur = hnext; hnext = t;
    }

    scores_kernel<<<(NN / 4) * NN / 256, 256>>>(out);
}

// round 15
// speedup vs baseline: 1.2150x; 1.1522x over previous
#include <cuda_runtime.h>
#include <cuda_fp16.h>
#include <stdint.h>

#define NN 4096
#define H 64
#define FIN 8
#define SPLITK 8
#define KCHUNK (NN / SPLITK)   /* 512 */
#define NCHUNK (KCHUNK / 64)   /* 8 chunks of K=64 */
#define MROWS 16               /* grid 256 >= 148 SMs */
#define HSCL  (1.0f / 1024.0f)
#define HUNSCL 1024.0f

// -------- persistent scratch (no device allocations allowed) --------
__device__ __half g_Af[(size_t)NN * NN];     // A in fp16, row-major
__device__ __half g_hTf[(size_t)H * NN];     // (h*HSCL)^T fp16: [n][k], K-major
__device__ float g_h0[NN * H];
__device__ float g_h1[NN * H];
__device__ float g_part[SPLITK][NN * H];
__device__ float g_si[NN];
__device__ float g_sj[NN];

// ---------------- helpers ----------------
__device__ __forceinline__ uint32_t smem_u32(const void* p) {
    uint32_t a;
    asm("{ .reg .u64 t; cvta.to.shared.u64 t, %1; cvt.u32.u64 %0, t; }"
        : "=r"(a) : "l"(p));
    return a;
}
#define SW128(off) ((off) ^ (((off) >> 3) & 0x70))
#define CP_ASYNC16(dst, src) \
    asm volatile("cp.async.cg.shared.global [%0], [%1], 16;" :: "r"(dst), "l"(src))
#define CP_COMMIT() asm volatile("cp.async.commit_group;" ::: "memory")
#define CP_WAIT(n)  asm volatile("cp.async.wait_group %0;" :: "n"(n) : "memory")

#define LDSM_X4(r0, r1, r2, r3, addr) \
    asm volatile("ldmatrix.sync.aligned.m8n8.x4.shared.b16 {%0,%1,%2,%3}, [%4];" \
        : "=r"(r0), "=r"(r1), "=r"(r2), "=r"(r3) : "r"(addr))

#define MMA_F16(c, a, b0v, b1v) \
    asm volatile("mma.sync.aligned.m16n8k16.row.col.f32.f16.f16.f32 " \
        "{%0,%1,%2,%3}, {%4,%5,%6,%7}, {%8,%9}, {%0,%1,%2,%3};" \
        : "+f"((c)[0]), "+f"((c)[1]), "+f"((c)[2]), "+f"((c)[3]) \
        : "r"((a)[0]), "r"((a)[1]), "r"((a)[2]), "r"((a)[3]), "r"(b0v), "r"(b1v))

// ============================================================
// convA: A fp32 -> fp16 (once per launch; A in [0,1))
// ============================================================
__global__ void convA_kernel(const float* __restrict__ A) {
    size_t t = (size_t)blockIdx.x * 256 + threadIdx.x;   // one per 8 floats
    const float4* a4 = reinterpret_cast<const float4*>(A);
    float4 a = a4[2 * t], b = a4[2 * t + 1];
    __half2 p0 = __floats2half2_rn(a.x, a.y);
    __half2 p1 = __floats2half2_rn(a.z, a.w);
    __half2 p2 = __floats2half2_rn(b.x, b.y);
    __half2 p3 = __floats2half2_rn(b.z, b.w);
    uint4 u;
    u.x = *reinterpret_cast<uint32_t*>(&p0);
    u.y = *reinterpret_cast<uint32_t*>(&p1);
    u.z = *reinterpret_cast<uint32_t*>(&p2);
    u.w = *reinterpret_cast<uint32_t*>(&p3);
    reinterpret_cast<uint4*>(g_Af)[t] = u;
}

// ============================================================
// Encoder: h0 = relu(X @ W_enc^T + b_enc); also writes scaled hT fp16.
// ============================================================
__global__ void enc_kernel(const float* __restrict__ X,
                           const float* __restrict__ We,
                           const float* __restrict__ be,
                           float* __restrict__ hout) {
    __shared__ float Ws[H][FIN];
    __shared__ float bs[H];
    __shared__ float hsm[4][64];
    int tid = threadIdx.x;
    for (int i = tid; i < H * FIN; i += 256) Ws[i / FIN][i % FIN] = We[i];
    if (tid < H) bs[tid] = be[tid];
    __syncthreads();
    int idx = blockIdx.x * 256 + tid;
    int i = idx >> 6, j = idx & 63;
    const float* xr = X + i * FIN;
    float acc = bs[j];
#pragma unroll
    for (int f = 0; f < FIN; f++) acc += xr[f] * Ws[j][f];
    float v = fmaxf(acc, 0.0f);
    hout[idx] = v;
    hsm[tid >> 6][j] = v;
    __syncthreads();
    int n = tid >> 2, kl = tid & 3;
    int kb = blockIdx.x * 4;
    g_hTf[(size_t)n * NN + kb + kl] = __float2half_rn(hsm[kl][n] * HSCL);
}

// ============================================================
// fp16 HMMA GEMM: part[sk] = A[:, sk*512:+512] @ (h*HSCL)[sk*512:+512]
// grid (32, 8) x 256 thr. CTA tile 128x64, BK=64, 2-stage cp.async.
// ============================================================
#define STAGE_BYTES 24576       /* 16KB A + 8KB B */
#define B_SOFF 16384
#define SMEM_TOTAL (2 * STAGE_BYTES)   /* 49152 */

__device__ __forceinline__ void load_chunk(uint32_t smem_base, int s, int k0,
                                           int tid, int mbase) {
    const char* Ab = reinterpret_cast<const char*>(g_Af);
    const char* Hb = reinterpret_cast<const char*>(g_hTf);
    uint32_t abase = smem_base + s * STAGE_BYTES;
    uint32_t bbase = smem_base + B_SOFF + s * STAGE_BYTES;
#pragma unroll
    for (int it = 0; it < 4; it++) {                 // A: 128 rows x 128B
        int c = tid + it * 256;
        int row = c >> 3, j = c & 7;
        uint32_t off = (uint32_t)(row * 128 + j * 16);
        const char* src = Ab + ((size_t)(mbase + row) * NN + k0) * 2 + j * 16;
        CP_ASYNC16(abase + SW128(off), src);
    }
#pragma unroll
    for (int it = 0; it < 2; it++) {                 // B: 64 n-rows x 128B
        int c = tid + it * 256;
        int n = c >> 3, j = c & 7;
        uint32_t off = (uint32_t)(n * 128 + j * 16);
        const char* src = Hb + ((size_t)n * NN + k0) * 2 + j * 16;
        CP_ASYNC16(bbase + SW128(off), src);
    }
    CP_COMMIT();
}

__global__ __launch_bounds__(256, 2)
void gemm_mma_kernel() {
    extern __shared__ __align__(1024) char smem[];
    const uint32_t smem_base = smem_u32(smem);
    const int tid = threadIdx.x;
    const int wid = tid >> 5;
    const int lane = tid & 31;
    const int warp_m = wid >> 2;
    const int warp_n = wid & 3;
    const int mbase = blockIdx.x * 128;
    const int kbase = blockIdx.y * KCHUNK;

    float acc[4][2][4];
#pragma unroll
    for (int mt = 0; mt < 4; mt++)
#pragma unroll
        for (int nt = 0; nt < 2; nt++)
#pragma unroll
            for (int e = 0; e < 4; e++) acc[mt][nt][e] = 0.0f;

    const int a_row = lane & 15;
    const int a_khalf = (lane >> 4) * 16;
    const int b_m = lane >> 3;
    const int b_r = lane & 7;
    const int b_n = ((b_m >> 1) << 3) + b_r;
    const int b_khalf = (b_m & 1) * 16;

    load_chunk(smem_base, 0, kbase, tid, mbase);

#pragma unroll 1
    for (int i = 0; i < NCHUNK; i++) {
        const int s = i & 1;
        if (i + 1 < NCHUNK) {
            load_chunk(smem_base, (i + 1) & 1, kbase + (i + 1) * 64, tid, mbase);
            CP_WAIT(1);
        } else {
            CP_WAIT(0);
        }
        __syncthreads();

        const uint32_t abase = smem_base + s * STAGE_BYTES;
        const uint32_t bbase = smem_base + B_SOFF + s * STAGE_BYTES;
#pragma unroll
        for (int ks = 0; ks < 4; ks++) {
            uint32_t b[4];
            {
                uint32_t off = (uint32_t)((warp_n * 16 + b_n) * 128 +
                                          ks * 32 + b_khalf);
                LDSM_X4(b[0], b[1], b[2], b[3], bbase + SW128(off));
            }
#pragma unroll
            for (int mt = 0; mt < 4; mt++) {
                uint32_t a[4];
                uint32_t off = (uint32_t)((warp_m * 64 + mt * 16 + a_row) * 128 +
                                          ks * 32 + a_khalf);
                LDSM_X4(a[0], a[1], a[2], a[3], abase + SW128(off));
                MMA_F16(acc[mt][0], a, b[0], b[1]);
                MMA_F16(acc[mt][1], a, b[2], b[3]);
            }
        }
        __syncthreads();
    }

    float* out = g_part[blockIdx.y];
    const int r0 = mbase + warp_m * 64 + (lane >> 2);
    const int c0 = warp_n * 16 + (lane & 3) * 2;
#pragma unroll
    for (int mt = 0; mt < 4; mt++) {
#pragma unroll
        for (int nt = 0; nt < 2; nt++) {
            int col = c0 + nt * 8;
            float2 lo = make_float2(acc[mt][nt][0], acc[mt][nt][1]);
            float2 hi = make_float2(acc[mt][nt][2], acc[mt][nt][3]);
            *reinterpret_cast<float2*>(&out[(size_t)(r0 + mt * 16) * H + col]) = lo;
            *reinterpret_cast<float2*>(&out[(size_t)(r0 + mt * 16 + 8) * H + col]) = hi;
        }
    }
}

// ============================================================
// MLP: hout = relu([h, HUNSCL*sum part] @ W^T + b)
// 256 blocks x 256 thr, 16 rows/block. Thread tile: 4 cols x 1 row.
// W staged transposed (c-major) -> float4 weight loads; float4 global
// staging for W, h, and g_part. Writes scaled hT fp16 (non-last);
// last layer computes s_i/s_j.
// ============================================================
#define WSTR 68   /* transposed-W row stride in floats, 16B-aligned */
__global__ __launch_bounds__(256, 3)
void mlp_kernel(const float* __restrict__ hin, const float* __restrict__ W,
                const float* __restrict__ b, float* __restrict__ hout,
                int last, const float* __restrict__ Wedge,
                const float* __restrict__ bedge) {
    __shared__ __align__(16) float W1T[H][WSTR];   // [c][col] = W[col][c]
    __shared__ __align__(16) float W2T[H][WSTR];   // [c][col] = W[col][H+c]
    __shared__ float h_s[MROWS][H + 1];
    __shared__ float hn_s[MROWS][H + 1];
    __shared__ float ho_s[MROWS][H];
    __shared__ float wedge[2 * H];
    const int tid = threadIdx.x;
    const int rbase = blockIdx.x * MROWS;

    // stage W transposed with float4 global reads (2048 float4, 8/thread)
    for (int v = tid; v < (H * 2 * H) / 4; v += 256) {
        float4 w = reinterpret_cast<const float4*>(W)[v];
        int col = v >> 5;            // 32 float4 per 128-float row
        int c = (v & 31) * 4;        // 0..124, same half for all 4 lanes
        if (c < H) {
            W1T[c + 0][col] = w.x; W1T[c + 1][col] = w.y;
            W1T[c + 2][col] = w.z; W1T[c + 3][col] = w.w;
        } else {
            int cc = c - H;
            W2T[cc + 0][col] = w.x; W2T[cc + 1][col] = w.y;
            W2T[cc + 2][col] = w.z; W2T[cc + 3][col] = w.w;
        }
    }
    if (last && tid < 2 * H) wedge[tid] = Wedge[tid];
    // stage h + reduced neighbor sums, float4 reads (1+8 LDG.128/thread)
    {
        int r = tid >> 4;            // 16 float4 per row
        int q = tid & 15;
        int c4 = q * 4;
        float4 hv = reinterpret_cast<const float4*>(
            hin + (size_t)(rbase + r) * H)[q];
        float4 s = make_float4(0.f, 0.f, 0.f, 0.f);
#pragma unroll
        for (int p = 0; p < SPLITK; p++) {
            float4 t = reinterpret_cast<const float4*>(
                &g_part[p][(size_t)(rbase + r) * H])[q];
            s.x += t.x; s.y += t.y; s.z += t.z; s.w += t.w;
        }
        h_s[r][c4] = hv.x; h_s[r][c4 + 1] = hv.y;
        h_s[r][c4 + 2] = hv.z; h_s[r][c4 + 3] = hv.w;
        hn_s[r][c4] = s.x * HUNSCL; hn_s[r][c4 + 1] = s.y * HUNSCL;
        hn_s[r][c4 + 2] = s.z * HUNSCL; hn_s[r][c4 + 3] = s.w * HUNSCL;
    }
    __syncthreads();

    // compute: thread tile 4 cols x 1 row
    const int tx = tid & 15;
    const int ty = tid >> 4;       // row 0..15
    const int col0 = tx * 4;
    float a0 = 0.f, a1 = 0.f, a2 = 0.f, a3 = 0.f;
#pragma unroll
    for (int c = 0; c < H; c++) {
        float4 w1 = *reinterpret_cast<const float4*>(&W1T[c][col0]);
        float4 w2 = *reinterpret_cast<const float4*>(&W2T[c][col0]);
        float hv = h_s[ty][c];     // broadcast across tx
        float hnv = hn_s[ty][c];
        a0 += hv * w1.x + hnv * w2.x;
        a1 += hv * w1.y + hnv * w2.y;
        a2 += hv * w1.z + hnv * w2.z;
        a3 += hv * w1.w + hnv * w2.w;
    }
    {
        const float4 bb = *reinterpret_cast<const float4*>(b + col0);
        float4 v = make_float4(fmaxf(a0 + bb.x, 0.f), fmaxf(a1 + bb.y, 0.f),
                               fmaxf(a2 + bb.z, 0.f), fmaxf(a3 + bb.w, 0.f));
        *reinterpret_cast<float4*>(&hout[(size_t)(rbase + ty) * H + col0]) = v;
        ho_s[ty][col0] = v.x; ho_s[ty][col0 + 1] = v.y;
        ho_s[ty][col0 + 2] = v.z; ho_s[ty][col0 + 3] = v.w;
    }
    __syncthreads();

    if (!last) {
        // transpose-write scaled hT fp16: n = i>>4 (0..63), kl = i&15
        for (int i = tid; i < H * MROWS; i += 256) {
            int n = i >> 4, kl = i & 15;
            g_hTf[(size_t)n * NN + rbase + kl] =
                __float2half_rn(ho_s[kl][n] * HSCL);
        }
    } else {
        if (tid < MROWS) {
            int r = tid;
            float a = 0.0f, bb2 = 0.0f;
#pragma unroll
            for (int c = 0; c < H; c++) {
                float hv = ho_s[r][c];
                a += hv * wedge[c];
                bb2 += hv * wedge[H + c];
            }
            g_si[rbase + r] = a + bedge[0];
            g_sj[rbase + r] = bb2;
        }
    }
}

// ============================================================
// scores[i][j] = s_i[i] + s_j[j], diag zeroed. float4 stores.
// ============================================================
__global__ void scores_kernel(float* __restrict__ out) {
    int idx = blockIdx.x * 256 + threadIdx.x;
    int i = idx >> 10;
    int j4 = (idx & 1023) << 2;
    float si = g_si[i];
    float4 sj = *reinterpret_cast<const float4*>(&g_sj[j4]);
    float4 v = make_float4(si + sj.x, si + sj.y, si + sj.z, si + sj.w);
    int d = i - j4;
    if (d >= 0 && d < 4) ((float*)&v)[d] = 0.0f;
    reinterpret_cast<float4*>(out)[idx] = v;
}

// ============================================================
extern "C" void kernel_launch(void* const* d_in, const int* in_sizes, int n_in,
                              void* d_out, int out_size) {
    const float* X     = (const float*)d_in[0];
    const float* Adj   = (const float*)d_in[1];
    const float* We    = (const float*)d_in[2];
    const float* be    = (const float*)d_in[3];
    const float* Wl[3] = {(const float*)d_in[4], (const float*)d_in[6],
                          (const float*)d_in[8]};
    const float* bl[3] = {(const float*)d_in[5], (const float*)d_in[7],
                          (const float*)d_in[9]};
    const float* Wedge = (const float*)d_in[10];
    const float* bedge = (const float*)d_in[11];
    float* out = (float*)d_out;

    cudaFuncSetAttribute(gemm_mma_kernel,
                         cudaFuncAttributeMaxDynamicSharedMemorySize, SMEM_TOTAL);

    float *ph0 = nullptr, *ph1 = nullptr;
    cudaGetSymbolAddress((void**)&ph0, g_h0);
    cudaGetSymbolAddress((void**)&ph1, g_h1);

    convA_kernel<<<(NN * NN / 8) / 256, 256>>>(Adj);
    enc_kernel<<<NN * H / 256, 256>>>(X, We, be, ph0);

    float* hcur = ph0;
    float* hnext = ph1;
    for (int l = 0; l < 3; l++) {
        gemm_mma_kernel<<<dim3(NN / 128, SPLITK), 256, SMEM_TOTAL>>>();
        mlp_kernel<<<NN / MROWS, 256>>>(hcur, Wl[l], bl[l], hnext,
                                        (l == 2) ? 1 : 0, Wedge, bedge);
        float* t = hcur; hcur = hnext; hnext = t;
    }

    scores_kernel<<<(NN / 4) * NN / 256, 256>>>(out);
}